// round 5
// baseline (speedup 1.0000x reference)
#include <cuda_runtime.h>
#include <math.h>

#define C_CH   192
#define HW     56
#define NPIX   3136      // 56*56
#define NBATCH 64
#define NPLANE 12288     // 64*192
#define NCELL  602112    // 12288*49
#define N4TOT  9633792   // 64*192*3136/4
#define POOLBLK 1344     // NCELL/448

__constant__ float c_lowx[32] = {0,0,1,1,0,2,2,1,2,0,3,4,0,1,3,0,1,2,3,4,5,0,1,2,3,4,5,6,1,2,3,4};
__constant__ float c_lowy[32] = {0,1,0,1,2,0,1,2,2,3,0,0,4,3,1,5,4,3,2,1,0,6,5,4,3,2,1,0,6,5,4,3};

// Scratch (no allocations allowed -> __device__ globals)
__device__ float g_part[56 * 32];        // per-row gate partial sums (n=0 only)
__device__ float g_xp[NCELL];            // adaptive-avg-pooled x
__device__ float g_w1dT[192 * 192];      // transposed center tap of w1d: [c][o]
__device__ float g_scale[NPLANE];        // final per-(n,c) scale

// ---------------------------------------------------------------------------
// Fused gate+pool kernel (36-reg cap, 4x448 = 1792 thr/SM).
//   blocks 0..55     : gate conv for batch element 0, one block per image row.
//   blocks 56..1399  : pool, thread-per-cell: each thread sums one 8x8 block
//                      via 16 LDG.128 (high MLP, no syncs, no smem) -> g_xp.
//                      First 83 pool blocks also transpose w1d's center tap.
// ---------------------------------------------------------------------------
__global__ __launch_bounds__(448, 4) void poolgate_kernel(
    const float* __restrict__ x, const float* __restrict__ wg1,
    const float* __restrict__ bng, const float* __restrict__ bnb,
    const float* __restrict__ bnm, const float* __restrict__ bnv,
    const float* __restrict__ w1d)
{
    __shared__ float smem[192 * 32 + 56 * 33];  // used only by gate blocks
    int t = threadIdx.x;
    int b = blockIdx.x;

    if (b < 56) {
        // ---------------- gate path ----------------
        float* sw    = smem;             // [192*32] sw[c*32+o] = wg1[o][c]
        float* sconv = smem + 192 * 32;  // [56*33] padded

        for (int i = t; i < 192 * 32; i += 448) {
            int c = i >> 5, o = i & 31;
            sw[i] = wg1[o * 192 + c];
        }
        for (int i = t; i < 56 * 33; i += 448) sconv[i] = 0.0f;
        __syncthreads();

        int px = t % 56;
        int q  = t / 56;                              // 0..7
        const float* xr = x + b * 56 + px;            // n=0, row=b
        float* dst = sconv + px * 33;
        int c0 = q * 24;

        for (int pass = 0; pass < 4; pass++) {
            int o0 = pass * 8;
            float acc[8];
#pragma unroll
            for (int u = 0; u < 8; u++) acc[u] = 0.0f;
#pragma unroll 4
            for (int c = c0; c < c0 + 24; c++) {
                float xv = __ldg(xr + c * NPIX);      // pass>0: L1 hit
                const float* w = sw + c * 32 + o0;
#pragma unroll
                for (int u = 0; u < 8; u++) acc[u] = fmaf(w[u], xv, acc[u]);
            }
#pragma unroll
            for (int u = 0; u < 8; u++) atomicAdd(dst + o0 + u, acc[u]);
        }
        __syncthreads();

        if (t < 32) {
            int o = t;
            float sc = bng[o] / sqrtf(bnv[o] + 1e-5f);
            float sh = bnb[o] - bnm[o] * sc;
            float s = 0.0f;
            for (int p = 0; p < 56; p++) {
                float v = fmaf(sconv[p * 33 + o], sc, sh);
                s += fmaxf(v, 0.0f);
            }
            g_part[b * 32 + o] = s;
        }
    } else {
        // ---------------- pool path (thread-per-cell, syncless) ----------------
        int pb = b - 56;

        if (pb < 83) {                   // w1d center-tap transpose
            int i = pb * 448 + t;
            if (i < 192 * 192) {
                int o = i % 192, cc = i / 192;
                g_w1dT[i] = w1d[o * 576 + cc * 3 + 1];   // [c][o] layout
            }
        }

        int cid = pb * 448 + t;          // = nc*49 + i7*7 + j
        int j   = cid % 7;
        int tmp = cid / 7;
        int i7  = tmp % 7;
        int nc  = tmp / 7;

        const float4* p = (const float4*)(x + (size_t)nc * NPIX + i7 * 8 * 56 + j * 8);
        float s = 0.0f;
#pragma unroll
        for (int r = 0; r < 8; r++) {
            float4 a = __ldg(p + r * 14);
            float4 c = __ldg(p + r * 14 + 1);
            s += (a.x + a.y + a.z + a.w) + (c.x + c.y + c.z + c.w);
        }
        g_xp[cid] = s * (1.0f / 64.0f);
    }
}

// ---------------------------------------------------------------------------
// Scale kernel: one block per batch element (64 blocks, 192 threads).
// ---------------------------------------------------------------------------
__global__ __launch_bounds__(192) void scale_kernel(
    const float* __restrict__ wg2, const float* __restrict__ bg2,
    const float* __restrict__ beta, const float* __restrict__ b1d,
    const float* __restrict__ bn1g, const float* __restrict__ bn1b,
    const float* __restrict__ bn1m, const float* __restrict__ bn1v)
{
    __shared__ float sg[32];
    __shared__ float sxg[32];
    __shared__ float sparam[33];
    __shared__ float sbasis[32 * 49];
    __shared__ float syin[192];

    int n = blockIdx.x, t = threadIdx.x;

    if (t < 32) {
        float s = 0.0f;
        for (int b = 0; b < 56; b++) s += g_part[b * 32 + t];
        sg[t] = s * (1.0f / 3136.0f);
    }
    __syncthreads();
    if (t < 32) {
        float a = bg2[t];
        for (int k = 0; k < 32; k++) a = fmaf(wg2[t * 32 + k], sg[k], a);
        sxg[t] = fmaxf(tanhf(a), 0.0f) + beta[0];
    }
    __syncthreads();
    if (t == 0) {
        float s = 0.0f;
        for (int i = 0; i < 32; i++) s += sxg[i];
        sparam[0] = 0.0f;
        float tot = 0.0f;
        for (int i = 1; i <= 31; i++) {
            float pv = rintf(sxg[i - 1] / s * 192.0f);  // rintf == jnp.round (half-even)
            sparam[i] = pv;
            tot += pv;
        }
        sparam[32] = 192.0f - tot;
    }
    const float PI = 3.14159265358979323846f;
    const float INV_SQRT7 = 0.37796447300922722721f;
    const float SQRT2 = 1.41421356237309504880f;
    for (int idx = t; idx < 32 * 49; idx += 192) {
        int bi = idx / 49, k = idx % 49;
        int tx = k / 7, ty = k % 7;
        float fx = c_lowx[bi], fy = c_lowy[bi];
        float bx = cosf(PI * fx * (tx + 0.5f) / 7.0f) * INV_SQRT7;
        if (fx != 0.0f) bx *= SQRT2;
        float by = cosf(PI * fy * (ty + 0.5f) / 7.0f) * INV_SQRT7;
        if (fy != 0.0f) by *= SQRT2;
        sbasis[idx] = bx * by;
    }
    __syncthreads();

    // yin[c]: last segment i with param[i] <= c < param[i+1] wins
    {
        float cf = (float)t;
        int bid = -1;
        for (int i = 0; i < 32; i++)
            if (cf >= sparam[i] && cf < sparam[i + 1]) bid = i;
        float yv = 0.0f;
        if (bid >= 0) {
            const float* xpp = g_xp + (n * 192 + t) * 49;
            const float* bb = sbasis + bid * 49;
#pragma unroll
            for (int k = 0; k < 49; k++) yv = fmaf(xpp[k], bb[k], yv);
        }
        syin[t] = yv;
    }
    __syncthreads();

    {
        float a = b1d[t];
        for (int c = 0; c < 192; c++) a = fmaf(g_w1dT[c * 192 + t], syin[c], a);
        float sc = bn1g[t] / sqrtf(bn1v[t] + 1e-5f);
        a = (a - bn1m[t]) * sc + bn1b[t];
        g_scale[n * 192 + t] = fmaxf(a, 0.0f);
    }
}

// ---------------------------------------------------------------------------
// Final kernel: out = x * (1 + scale[n,c]).  Reverse address order -> early
// reads hit the x-tail still in L2 after the pool pass; streaming stores keep
// the output from evicting x.
// ---------------------------------------------------------------------------
__global__ __launch_bounds__(256) void final_kernel(
    const float* __restrict__ x, float* __restrict__ out)
{
    const float4* x4 = (const float4*)x;
    float4* o4 = (float4*)out;
    int i = blockIdx.x * blockDim.x + threadIdx.x;
    int r = N4TOT - 1 - i;
    int nc = r / 784;                       // 784 float4 per (n,c) plane
    float s = 1.0f + __ldg(&g_scale[nc]);
    float4 v = __ldg(x4 + r);
    v.x *= s; v.y *= s; v.z *= s; v.w *= s;
    __stcs(o4 + r, v);
}

// ---------------------------------------------------------------------------
// Inputs (metadata order): x, wg1, bn2_g, bn2_b, bn2_m, bn2_v,
//                          wg2, bg2, beta, w1d, b1d, bn1_g, bn1_b, bn1_m, bn1_v
// ---------------------------------------------------------------------------
extern "C" void kernel_launch(void* const* d_in, const int* in_sizes, int n_in,
                              void* d_out, int out_size)
{
    const float* x     = (const float*)d_in[0];
    const float* wg1   = (const float*)d_in[1];
    const float* bn2g  = (const float*)d_in[2];
    const float* bn2b  = (const float*)d_in[3];
    const float* bn2m  = (const float*)d_in[4];
    const float* bn2v  = (const float*)d_in[5];
    const float* wg2   = (const float*)d_in[6];
    const float* bg2   = (const float*)d_in[7];
    const float* beta  = (const float*)d_in[8];
    const float* w1d   = (const float*)d_in[9];
    const float* b1d   = (const float*)d_in[10];
    const float* bn1g  = (const float*)d_in[11];
    const float* bn1b  = (const float*)d_in[12];
    const float* bn1m  = (const float*)d_in[13];
    const float* bn1v  = (const float*)d_in[14];
    float* out = (float*)d_out;

    poolgate_kernel<<<56 + POOLBLK, 448>>>(x, wg1, bn2g, bn2b, bn2m, bn2v, w1d);
    scale_kernel<<<64, 192>>>(wg2, bg2, beta, b1d, bn1g, bn1b, bn1m, bn1v);
    final_kernel<<<N4TOT / 256, 256>>>(x, out);
}

// round 6
// speedup vs baseline: 1.2087x; 1.2087x over previous
#include <cuda_runtime.h>
#include <math.h>

#define C_CH   192
#define HW     56
#define NPIX   3136      // 56*56
#define NBATCH 64
#define NPLANE 12288     // 64*192
#define NCELL  602112    // 12288*49
#define N4TOT  9633792   // 64*192*3136/4
#define PPB    4         // planes per pool block
#define POOLBLK (NPLANE / PPB)   // 3072

__constant__ float c_lowx[32] = {0,0,1,1,0,2,2,1,2,0,3,4,0,1,3,0,1,2,3,4,5,0,1,2,3,4,5,6,1,2,3,4};
__constant__ float c_lowy[32] = {0,1,0,1,2,0,1,2,2,3,0,0,4,3,1,5,4,3,2,1,0,6,5,4,3,2,1,0,6,5,4,3};

// Scratch (no allocations allowed -> __device__ globals)
__device__ float g_part[56 * 32];        // per-row gate partial sums (n=0 only)
__device__ float g_xp[NCELL];            // adaptive-avg-pooled x
__device__ float g_w1dT[192 * 192];      // transposed center tap of w1d: [c][o]
__device__ float g_scale[NPLANE];        // final per-(n,c) scale

// ---------------------------------------------------------------------------
// Fused gate+pool kernel (36-reg cap, 4 blocks/SM = 1792 thr).
//   blocks 0..55      : gate conv for batch element 0, one block per image row.
//   blocks 56..3127   : pool, 4 planes per block. Thread t<392 loads 2 float4
//                       from each of 4 planes. Warp loads are FULLY contiguous
//                       (byte offset = t*32 within each plane). Two MLP-4 load
//                       batches -> ~2x load duty vs one-plane blocks. Then one
//                       sync and a 196-thread reduce (4 planes x 49 cells).
// ---------------------------------------------------------------------------
__global__ __launch_bounds__(448, 4) void poolgate_kernel(
    const float* __restrict__ x, const float* __restrict__ wg1,
    const float* __restrict__ bng, const float* __restrict__ bnb,
    const float* __restrict__ bnm, const float* __restrict__ bnv,
    const float* __restrict__ w1d)
{
    __shared__ float smem[192 * 32 + 56 * 33];  // gate: 31.9KB; pool uses 1568
    int t = threadIdx.x;
    int b = blockIdx.x;

    if (b < 56) {
        // ---------------- gate path ----------------
        float* sw    = smem;             // [192*32] sw[c*32+o] = wg1[o][c]
        float* sconv = smem + 192 * 32;  // [56*33] padded

        for (int i = t; i < 192 * 32; i += 448) {
            int c = i >> 5, o = i & 31;
            sw[i] = wg1[o * 192 + c];
        }
        for (int i = t; i < 56 * 33; i += 448) sconv[i] = 0.0f;
        __syncthreads();

        int px = t % 56;
        int q  = t / 56;                              // 0..7
        const float* xr = x + b * 56 + px;            // n=0, row=b
        float* dst = sconv + px * 33;
        int c0 = q * 24;

        for (int pass = 0; pass < 4; pass++) {
            int o0 = pass * 8;
            float acc[8];
#pragma unroll
            for (int u = 0; u < 8; u++) acc[u] = 0.0f;
#pragma unroll 4
            for (int c = c0; c < c0 + 24; c++) {
                float xv = __ldg(xr + c * NPIX);      // pass>0: L1 hit
                const float* w = sw + c * 32 + o0;
#pragma unroll
                for (int u = 0; u < 8; u++) acc[u] = fmaf(w[u], xv, acc[u]);
            }
#pragma unroll
            for (int u = 0; u < 8; u++) atomicAdd(dst + o0 + u, acc[u]);
        }
        __syncthreads();

        if (t < 32) {
            int o = t;
            float sc = bng[o] / sqrtf(bnv[o] + 1e-5f);
            float sh = bnb[o] - bnm[o] * sc;
            float s = 0.0f;
            for (int p = 0; p < 56; p++) {
                float v = fmaf(sconv[p * 33 + o], sc, sh);
                s += fmaxf(v, 0.0f);
            }
            g_part[b * 32 + o] = s;
        }
    } else {
        // ---------------- pool path ----------------
        int pb  = b - 56;
        int nc0 = pb * PPB;

        if (pb < 83) {                   // w1d center-tap transpose
            int i = pb * 448 + t;
            if (i < 192 * 192) {
                int o = i % 192, cc = i / 192;
                g_w1dT[i] = w1d[o * 576 + cc * 3 + 1];   // [c][o] layout
            }
        }

        if (t < 392) {
            // byte offset within plane = t*32 -> warp reads 1KB contiguous
            const float4* p0 = (const float4*)(x + (size_t)nc0 * NPIX) + t * 2;
            // batch 1: planes 0,1 (MLP 4)
            float4 a0 = __ldg(p0);
            float4 c0 = __ldg(p0 + 1);
            float4 a1 = __ldg(p0 + 784);
            float4 c1 = __ldg(p0 + 785);
            float s0 = (a0.x + a0.y + a0.z + a0.w) + (c0.x + c0.y + c0.z + c0.w);
            float s1 = (a1.x + a1.y + a1.z + a1.w) + (c1.x + c1.y + c1.z + c1.w);
            // batch 2: planes 2,3
            float4 a2 = __ldg(p0 + 1568);
            float4 c2 = __ldg(p0 + 1569);
            float4 a3 = __ldg(p0 + 2352);
            float4 c3 = __ldg(p0 + 2353);
            float s2 = (a2.x + a2.y + a2.z + a2.w) + (c2.x + c2.y + c2.z + c2.w);
            float s3 = (a3.x + a3.y + a3.z + a3.w) + (c3.x + c3.y + c3.z + c3.w);
            smem[t]            = s0;
            smem[392 + t]      = s1;
            smem[784 + t]      = s2;
            smem[1176 + t]     = s3;
        }
        __syncthreads();
        if (t < 196) {                   // 4 planes x 49 cells
            int pl = t / 49, cell = t % 49;
            int ci = cell / 7, cj = cell % 7;
            const float* sp = smem + pl * 392 + cj;
            float s = 0.0f;
#pragma unroll
            for (int k = 0; k < 8; k++) s += sp[(ci * 8 + k) * 7];
            g_xp[(nc0 + pl) * 49 + cell] = s * (1.0f / 64.0f);
        }
    }
}

// ---------------------------------------------------------------------------
// Scale kernel: one block per batch element (64 blocks, 192 threads).
// ---------------------------------------------------------------------------
__global__ __launch_bounds__(192) void scale_kernel(
    const float* __restrict__ wg2, const float* __restrict__ bg2,
    const float* __restrict__ beta, const float* __restrict__ b1d,
    const float* __restrict__ bn1g, const float* __restrict__ bn1b,
    const float* __restrict__ bn1m, const float* __restrict__ bn1v)
{
    __shared__ float sg[32];
    __shared__ float sxg[32];
    __shared__ float sparam[33];
    __shared__ float sbasis[32 * 49];
    __shared__ float syin[192];

    int n = blockIdx.x, t = threadIdx.x;

    if (t < 32) {
        float s = 0.0f;
        for (int b = 0; b < 56; b++) s += g_part[b * 32 + t];
        sg[t] = s * (1.0f / 3136.0f);
    }
    __syncthreads();
    if (t < 32) {
        float a = bg2[t];
        for (int k = 0; k < 32; k++) a = fmaf(wg2[t * 32 + k], sg[k], a);
        sxg[t] = fmaxf(tanhf(a), 0.0f) + beta[0];
    }
    __syncthreads();
    if (t == 0) {
        float s = 0.0f;
        for (int i = 0; i < 32; i++) s += sxg[i];
        sparam[0] = 0.0f;
        float tot = 0.0f;
        for (int i = 1; i <= 31; i++) {
            float pv = rintf(sxg[i - 1] / s * 192.0f);  // rintf == jnp.round (half-even)
            sparam[i] = pv;
            tot += pv;
        }
        sparam[32] = 192.0f - tot;
    }
    const float PI = 3.14159265358979323846f;
    const float INV_SQRT7 = 0.37796447300922722721f;
    const float SQRT2 = 1.41421356237309504880f;
    for (int idx = t; idx < 32 * 49; idx += 192) {
        int bi = idx / 49, k = idx % 49;
        int tx = k / 7, ty = k % 7;
        float fx = c_lowx[bi], fy = c_lowy[bi];
        float bx = cosf(PI * fx * (tx + 0.5f) / 7.0f) * INV_SQRT7;
        if (fx != 0.0f) bx *= SQRT2;
        float by = cosf(PI * fy * (ty + 0.5f) / 7.0f) * INV_SQRT7;
        if (fy != 0.0f) by *= SQRT2;
        sbasis[idx] = bx * by;
    }
    __syncthreads();

    // yin[c]: last segment i with param[i] <= c < param[i+1] wins
    {
        float cf = (float)t;
        int bid = -1;
        for (int i = 0; i < 32; i++)
            if (cf >= sparam[i] && cf < sparam[i + 1]) bid = i;
        float yv = 0.0f;
        if (bid >= 0) {
            const float* xpp = g_xp + (n * 192 + t) * 49;
            const float* bb = sbasis + bid * 49;
#pragma unroll
            for (int k = 0; k < 49; k++) yv = fmaf(xpp[k], bb[k], yv);
        }
        syin[t] = yv;
    }
    __syncthreads();

    {
        float a = b1d[t];
        for (int c = 0; c < 192; c++) a = fmaf(g_w1dT[c * 192 + t], syin[c], a);
        float sc = bn1g[t] / sqrtf(bn1v[t] + 1e-5f);
        a = (a - bn1m[t]) * sc + bn1b[t];
        g_scale[n * 192 + t] = fmaxf(a, 0.0f);
    }
}

// ---------------------------------------------------------------------------
// Final kernel: out = x * (1 + scale[n,c]).  Reverse address order -> early
// reads hit the x-tail still in L2 after the pool pass; streaming stores keep
// the output from evicting x.
// ---------------------------------------------------------------------------
__global__ __launch_bounds__(256) void final_kernel(
    const float* __restrict__ x, float* __restrict__ out)
{
    const float4* x4 = (const float4*)x;
    float4* o4 = (float4*)out;
    int i = blockIdx.x * blockDim.x + threadIdx.x;
    int r = N4TOT - 1 - i;
    int nc = r / 784;                       // 784 float4 per (n,c) plane
    float s = 1.0f + __ldg(&g_scale[nc]);
    float4 v = __ldg(x4 + r);
    v.x *= s; v.y *= s; v.z *= s; v.w *= s;
    __stcs(o4 + r, v);
}

// ---------------------------------------------------------------------------
// Inputs (metadata order): x, wg1, bn2_g, bn2_b, bn2_m, bn2_v,
//                          wg2, bg2, beta, w1d, b1d, bn1_g, bn1_b, bn1_m, bn1_v
// ---------------------------------------------------------------------------
extern "C" void kernel_launch(void* const* d_in, const int* in_sizes, int n_in,
                              void* d_out, int out_size)
{
    const float* x     = (const float*)d_in[0];
    const float* wg1   = (const float*)d_in[1];
    const float* bn2g  = (const float*)d_in[2];
    const float* bn2b  = (const float*)d_in[3];
    const float* bn2m  = (const float*)d_in[4];
    const float* bn2v  = (const float*)d_in[5];
    const float* wg2   = (const float*)d_in[6];
    const float* bg2   = (const float*)d_in[7];
    const float* beta  = (const float*)d_in[8];
    const float* w1d   = (const float*)d_in[9];
    const float* b1d   = (const float*)d_in[10];
    const float* bn1g  = (const float*)d_in[11];
    const float* bn1b  = (const float*)d_in[12];
    const float* bn1m  = (const float*)d_in[13];
    const float* bn1v  = (const float*)d_in[14];
    float* out = (float*)d_out;

    poolgate_kernel<<<56 + POOLBLK, 448>>>(x, wg1, bn2g, bn2b, bn2m, bn2v, w1d);
    scale_kernel<<<64, 192>>>(wg2, bg2, beta, b1d, bn1g, bn1b, bn1m, bn1v);
    final_kernel<<<N4TOT / 256, 256>>>(x, out);
}

// round 7
// speedup vs baseline: 1.2813x; 1.0601x over previous
#include <cuda_runtime.h>
#include <math.h>

#define C_CH   192
#define HW     56
#define NPIX   3136      // 56*56
#define NBATCH 64
#define NPLANE 12288     // 64*192
#define NCELL  602112    // 12288*49
#define N4TOT  9633792   // 64*192*3136/4
#define PPB    8         // planes per pool block (pipelined)
#define POOLBLK (NPLANE / PPB)   // 1536

__constant__ float c_lowx[32] = {0,0,1,1,0,2,2,1,2,0,3,4,0,1,3,0,1,2,3,4,5,0,1,2,3,4,5,6,1,2,3,4};
__constant__ float c_lowy[32] = {0,1,0,1,2,0,1,2,2,3,0,0,4,3,1,5,4,3,2,1,0,6,5,4,3,2,1,0,6,5,4,3};

// Scratch (no allocations allowed -> __device__ globals)
__device__ float g_part[56 * 32];        // per-row gate partial sums (n=0 only)
__device__ float g_xp[NCELL];            // adaptive-avg-pooled x
__device__ float g_w1dT[192 * 192];      // transposed center tap of w1d: [c][o]
__device__ float g_scale[NPLANE];        // final per-(n,c) scale

// ---------------------------------------------------------------------------
// Fused gate+pool kernel. __launch_bounds__(448,3): <=48 regs, 3 blocks/SM.
//   blocks 0..55       : gate conv for batch element 0, one block per image row.
//   blocks 56..1591    : pool, 8 planes per block, SOFTWARE-PIPELINED:
//                        plane k+1's loads (2x float4/thread, warp-contiguous
//                        1KB) are issued BEFORE plane k's sync+reduce, so DRAM
//                        requests stay in flight across the whole block life.
// ---------------------------------------------------------------------------
__global__ __launch_bounds__(448, 3) void poolgate_kernel(
    const float* __restrict__ x, const float* __restrict__ wg1,
    const float* __restrict__ bng, const float* __restrict__ bnb,
    const float* __restrict__ bnm, const float* __restrict__ bnv,
    const float* __restrict__ w1d)
{
    __shared__ float smem[192 * 32 + 56 * 33];  // gate: 31.9KB; pool uses 392
    int t = threadIdx.x;
    int b = blockIdx.x;

    if (b < 56) {
        // ---------------- gate path ----------------
        float* sw    = smem;             // [192*32] sw[c*32+o] = wg1[o][c]
        float* sconv = smem + 192 * 32;  // [56*33] padded

        for (int i = t; i < 192 * 32; i += 448) {
            int c = i >> 5, o = i & 31;
            sw[i] = wg1[o * 192 + c];
        }
        for (int i = t; i < 56 * 33; i += 448) sconv[i] = 0.0f;
        __syncthreads();

        int px = t % 56;
        int q  = t / 56;                              // 0..7
        const float* xr = x + b * 56 + px;            // n=0, row=b
        float* dst = sconv + px * 33;
        int c0 = q * 24;

        for (int pass = 0; pass < 4; pass++) {
            int o0 = pass * 8;
            float acc[8];
#pragma unroll
            for (int u = 0; u < 8; u++) acc[u] = 0.0f;
#pragma unroll 4
            for (int c = c0; c < c0 + 24; c++) {
                float xv = __ldg(xr + c * NPIX);      // pass>0: L1 hit
                const float* w = sw + c * 32 + o0;
#pragma unroll
                for (int u = 0; u < 8; u++) acc[u] = fmaf(w[u], xv, acc[u]);
            }
#pragma unroll
            for (int u = 0; u < 8; u++) atomicAdd(dst + o0 + u, acc[u]);
        }
        __syncthreads();

        if (t < 32) {
            int o = t;
            float sc = bng[o] / sqrtf(bnv[o] + 1e-5f);
            float sh = bnb[o] - bnm[o] * sc;
            float s = 0.0f;
            for (int p = 0; p < 56; p++) {
                float v = fmaf(sconv[p * 33 + o], sc, sh);
                s += fmaxf(v, 0.0f);
            }
            g_part[b * 32 + o] = s;
        }
    } else {
        // ---------------- pool path (8 planes, pipelined) ----------------
        int pb  = b - 56;
        int nc0 = pb * PPB;

        if (pb < 83) {                   // w1d center-tap transpose
            int i = pb * 448 + t;
            if (i < 192 * 192) {
                int o = i % 192, cc = i / 192;
                g_w1dT[i] = w1d[o * 576 + cc * 3 + 1];   // [c][o] layout
            }
        }

        bool act = (t < 392);
        int tt = act ? t : 0;
        const float4* p4 = (const float4*)(x + (size_t)nc0 * NPIX) + tt * 2;

        // reduce-thread precompute
        int rci = (t % 49) / 7, rcj = (t % 49) % 7;
        const float* sp = smem + rci * 56 + rcj;     // stride-7 rows, base row rci*8

        float4 a, c;
        if (act) { a = __ldg(p4); c = __ldg(p4 + 1); }  // plane 0 prologue

#pragma unroll
        for (int k = 0; k < PPB; k++) {
            float s = act ? (a.x + a.y + a.z + a.w) + (c.x + c.y + c.z + c.w) : 0.0f;
            if (k + 1 < PPB && act) {                // prefetch plane k+1 EARLY
                a = __ldg(p4 + (k + 1) * 784);
                c = __ldg(p4 + (k + 1) * 784 + 1);
            }
            __syncthreads();                         // prev reduce done with smem
            if (act) smem[t] = s;
            __syncthreads();
            if (t < 49) {
                float r = 0.0f;
#pragma unroll
                for (int u = 0; u < 8; u++) r += sp[u * 7];
                g_xp[(nc0 + k) * 49 + t] = r * (1.0f / 64.0f);
            }
        }
    }
}

// ---------------------------------------------------------------------------
// Scale kernel: one block per batch element (64 blocks, 192 threads).
// ---------------------------------------------------------------------------
__global__ __launch_bounds__(192) void scale_kernel(
    const float* __restrict__ wg2, const float* __restrict__ bg2,
    const float* __restrict__ beta, const float* __restrict__ b1d,
    const float* __restrict__ bn1g, const float* __restrict__ bn1b,
    const float* __restrict__ bn1m, const float* __restrict__ bn1v)
{
    __shared__ float sg[32];
    __shared__ float sxg[32];
    __shared__ float sparam[33];
    __shared__ float sbasis[32 * 49];
    __shared__ float syin[192];

    int n = blockIdx.x, t = threadIdx.x;

    if (t < 32) {
        float s = 0.0f;
        for (int b = 0; b < 56; b++) s += g_part[b * 32 + t];
        sg[t] = s * (1.0f / 3136.0f);
    }
    __syncthreads();
    if (t < 32) {
        float a = bg2[t];
        for (int k = 0; k < 32; k++) a = fmaf(wg2[t * 32 + k], sg[k], a);
        sxg[t] = fmaxf(tanhf(a), 0.0f) + beta[0];
    }
    __syncthreads();
    if (t == 0) {
        float s = 0.0f;
        for (int i = 0; i < 32; i++) s += sxg[i];
        sparam[0] = 0.0f;
        float tot = 0.0f;
        for (int i = 1; i <= 31; i++) {
            float pv = rintf(sxg[i - 1] / s * 192.0f);  // rintf == jnp.round (half-even)
            sparam[i] = pv;
            tot += pv;
        }
        sparam[32] = 192.0f - tot;
    }
    const float PI = 3.14159265358979323846f;
    const float INV_SQRT7 = 0.37796447300922722721f;
    const float SQRT2 = 1.41421356237309504880f;
    for (int idx = t; idx < 32 * 49; idx += 192) {
        int bi = idx / 49, k = idx % 49;
        int tx = k / 7, ty = k % 7;
        float fx = c_lowx[bi], fy = c_lowy[bi];
        float bx = cosf(PI * fx * (tx + 0.5f) / 7.0f) * INV_SQRT7;
        if (fx != 0.0f) bx *= SQRT2;
        float by = cosf(PI * fy * (ty + 0.5f) / 7.0f) * INV_SQRT7;
        if (fy != 0.0f) by *= SQRT2;
        sbasis[idx] = bx * by;
    }
    __syncthreads();

    // yin[c]: last segment i with param[i] <= c < param[i+1] wins
    {
        float cf = (float)t;
        int bid = -1;
        for (int i = 0; i < 32; i++)
            if (cf >= sparam[i] && cf < sparam[i + 1]) bid = i;
        float yv = 0.0f;
        if (bid >= 0) {
            const float* xpp = g_xp + (n * 192 + t) * 49;
            const float* bb = sbasis + bid * 49;
#pragma unroll
            for (int k = 0; k < 49; k++) yv = fmaf(xpp[k], bb[k], yv);
        }
        syin[t] = yv;
    }
    __syncthreads();

    {
        float a = b1d[t];
        for (int c = 0; c < 192; c++) a = fmaf(g_w1dT[c * 192 + t], syin[c], a);
        float sc = bn1g[t] / sqrtf(bn1v[t] + 1e-5f);
        a = (a - bn1m[t]) * sc + bn1b[t];
        g_scale[n * 192 + t] = fmaxf(a, 0.0f);
    }
}

// ---------------------------------------------------------------------------
// Final kernel: out = x * (1 + scale[n,c]).  Reverse address order -> early
// reads hit the x-tail still in L2 after the pool pass; streaming stores keep
// the output from evicting x.
// ---------------------------------------------------------------------------
__global__ __launch_bounds__(256) void final_kernel(
    const float* __restrict__ x, float* __restrict__ out)
{
    const float4* x4 = (const float4*)x;
    float4* o4 = (float4*)out;
    int i = blockIdx.x * blockDim.x + threadIdx.x;
    int r = N4TOT - 1 - i;
    int nc = r / 784;                       // 784 float4 per (n,c) plane
    float s = 1.0f + __ldg(&g_scale[nc]);
    float4 v = __ldg(x4 + r);
    v.x *= s; v.y *= s; v.z *= s; v.w *= s;
    __stcs(o4 + r, v);
}

// ---------------------------------------------------------------------------
// Inputs (metadata order): x, wg1, bn2_g, bn2_b, bn2_m, bn2_v,
//                          wg2, bg2, beta, w1d, b1d, bn1_g, bn1_b, bn1_m, bn1_v
// ---------------------------------------------------------------------------
extern "C" void kernel_launch(void* const* d_in, const int* in_sizes, int n_in,
                              void* d_out, int out_size)
{
    const float* x     = (const float*)d_in[0];
    const float* wg1   = (const float*)d_in[1];
    const float* bn2g  = (const float*)d_in[2];
    const float* bn2b  = (const float*)d_in[3];
    const float* bn2m  = (const float*)d_in[4];
    const float* bn2v  = (const float*)d_in[5];
    const float* wg2   = (const float*)d_in[6];
    const float* bg2   = (const float*)d_in[7];
    const float* beta  = (const float*)d_in[8];
    const float* w1d   = (const float*)d_in[9];
    const float* b1d   = (const float*)d_in[10];
    const float* bn1g  = (const float*)d_in[11];
    const float* bn1b  = (const float*)d_in[12];
    const float* bn1m  = (const float*)d_in[13];
    const float* bn1v  = (const float*)d_in[14];
    float* out = (float*)d_out;

    poolgate_kernel<<<56 + POOLBLK, 448>>>(x, wg1, bn2g, bn2b, bn2m, bn2v, w1d);
    scale_kernel<<<64, 192>>>(wg2, bg2, beta, b1d, bn1g, bn1b, bn1m, bn1v);
    final_kernel<<<N4TOT / 256, 256>>>(x, out);
}

// round 9
// speedup vs baseline: 1.3397x; 1.0456x over previous
#include <cuda_runtime.h>
#include <math.h>

#define C_CH   192
#define HW     56
#define NPIX   3136      // 56*56
#define NBATCH 64
#define NPLANE 12288     // 64*192
#define NCELL  602112    // 12288*49
#define N4TOT  9633792   // 64*192*3136/4
#define PPB    2         // planes per pool block
#define POOLBLK (NPLANE / PPB)   // 6144

__constant__ float c_lowx[32] = {0,0,1,1,0,2,2,1,2,0,3,4,0,1,3,0,1,2,3,4,5,0,1,2,3,4,5,6,1,2,3,4};
__constant__ float c_lowy[32] = {0,1,0,1,2,0,1,2,2,3,0,0,4,3,1,5,4,3,2,1,0,6,5,4,3,2,1,0,6,5,4,3};

// Scratch (no allocations allowed -> __device__ globals)
__device__ float g_part[56 * 32];        // per-row gate partial sums (n=0 only)
__device__ float g_xp[NCELL];            // adaptive-avg-pooled x
__device__ float g_w1dT[192 * 192];      // transposed center tap of w1d: [c][o]
__device__ float g_scale[NPLANE];        // final per-(n,c) scale

// ---------------------------------------------------------------------------
// Fused gate+pool kernel. __launch_bounds__(448,3): <=48 regs, 3 blocks/SM.
//   blocks 0..55     : gate conv for batch element 0, one block per image row.
//   blocks 56..6199  : pool, 2 planes per block, ONE load phase with 4
//                      independent warp-contiguous LDG.128 per thread (16 data
//                      regs in flight -> ~75KB/SM outstanding), one sync,
//                      98-thread reduce, exit.
// ---------------------------------------------------------------------------
__global__ __launch_bounds__(448, 3) void poolgate_kernel(
    const float* __restrict__ x, const float* __restrict__ wg1,
    const float* __restrict__ bng, const float* __restrict__ bnb,
    const float* __restrict__ bnm, const float* __restrict__ bnv,
    const float* __restrict__ w1d)
{
    __shared__ float smem[192 * 32 + 56 * 33];  // gate: 31.9KB; pool uses 784
    int t = threadIdx.x;
    int b = blockIdx.x;

    if (b < 56) {
        // ---------------- gate path ----------------
        float* sw    = smem;             // [192*32] sw[c*32+o] = wg1[o][c]
        float* sconv = smem + 192 * 32;  // [56*33] padded

        for (int i = t; i < 192 * 32; i += 448) {
            int c = i >> 5, o = i & 31;
            sw[i] = wg1[o * 192 + c];
        }
        for (int i = t; i < 56 * 33; i += 448) sconv[i] = 0.0f;
        __syncthreads();

        int px = t % 56;
        int q  = t / 56;                              // 0..7
        const float* xr = x + b * 56 + px;            // n=0, row=b
        float* dst = sconv + px * 33;
        int c0 = q * 24;

        for (int pass = 0; pass < 4; pass++) {
            int o0 = pass * 8;
            float acc[8];
#pragma unroll
            for (int u = 0; u < 8; u++) acc[u] = 0.0f;
#pragma unroll 4
            for (int c = c0; c < c0 + 24; c++) {
                float xv = __ldg(xr + c * NPIX);      // pass>0: L1 hit
                const float* w = sw + c * 32 + o0;
#pragma unroll
                for (int u = 0; u < 8; u++) acc[u] = fmaf(w[u], xv, acc[u]);
            }
#pragma unroll
            for (int u = 0; u < 8; u++) atomicAdd(dst + o0 + u, acc[u]);
        }
        __syncthreads();

        if (t < 32) {
            int o = t;
            float sc = bng[o] / sqrtf(bnv[o] + 1e-5f);
            float sh = bnb[o] - bnm[o] * sc;
            float s = 0.0f;
            for (int p = 0; p < 56; p++) {
                float v = fmaf(sconv[p * 33 + o], sc, sh);
                s += fmaxf(v, 0.0f);
            }
            g_part[b * 32 + o] = s;
        }
    } else {
        // ---------------- pool path (2 planes, MLP-4 load phase) ----------------
        int pb  = b - 56;
        int nc0 = pb * PPB;

        if (pb < 83) {                   // w1d center-tap transpose
            int i = pb * 448 + t;
            if (i < 192 * 192) {
                int o = i % 192, cc = i / 192;
                g_w1dT[i] = w1d[o * 576 + cc * 3 + 1];   // [c][o] layout
            }
        }

        if (t < 392) {
            // byte offset within plane = t*32 -> each warp reads 1KB contiguous
            const float4* p = (const float4*)(x + (size_t)nc0 * NPIX) + t * 2;
            float4 a0 = __ldg(p);
            float4 c0 = __ldg(p + 1);
            float4 a1 = __ldg(p + 784);
            float4 c1 = __ldg(p + 785);
            smem[t]       = (a0.x + a0.y + a0.z + a0.w) + (c0.x + c0.y + c0.z + c0.w);
            smem[392 + t] = (a1.x + a1.y + a1.z + a1.w) + (c1.x + c1.y + c1.z + c1.w);
        }
        __syncthreads();
        if (t < 98) {                    // 2 planes x 49 cells
            int pl = t / 49, cell = t % 49;
            int ci = cell / 7, cj = cell % 7;
            const float* sp = smem + pl * 392 + ci * 56 + cj;
            float s = 0.0f;
#pragma unroll
            for (int u = 0; u < 8; u++) s += sp[u * 7];
            g_xp[(nc0 + pl) * 49 + cell] = s * (1.0f / 64.0f);
        }
    }
}

// ---------------------------------------------------------------------------
// Scale kernel: one block per batch element (64 blocks, 192 threads).
// ---------------------------------------------------------------------------
__global__ __launch_bounds__(192) void scale_kernel(
    const float* __restrict__ wg2, const float* __restrict__ bg2,
    const float* __restrict__ beta, const float* __restrict__ b1d,
    const float* __restrict__ bn1g, const float* __restrict__ bn1b,
    const float* __restrict__ bn1m, const float* __restrict__ bn1v)
{
    __shared__ float sg[32];
    __shared__ float sxg[32];
    __shared__ float sparam[33];
    __shared__ float sbasis[32 * 49];
    __shared__ float syin[192];

    int n = blockIdx.x, t = threadIdx.x;

    if (t < 32) {
        float s = 0.0f;
        for (int b = 0; b < 56; b++) s += g_part[b * 32 + t];
        sg[t] = s * (1.0f / 3136.0f);
    }
    __syncthreads();
    if (t < 32) {
        float a = bg2[t];
        for (int k = 0; k < 32; k++) a = fmaf(wg2[t * 32 + k], sg[k], a);
        sxg[t] = fmaxf(tanhf(a), 0.0f) + beta[0];
    }
    __syncthreads();
    if (t == 0) {
        float s = 0.0f;
        for (int i = 0; i < 32; i++) s += sxg[i];
        sparam[0] = 0.0f;
        float tot = 0.0f;
        for (int i = 1; i <= 31; i++) {
            float pv = rintf(sxg[i - 1] / s * 192.0f);  // rintf == jnp.round (half-even)
            sparam[i] = pv;
            tot += pv;
        }
        sparam[32] = 192.0f - tot;
    }
    const float PI = 3.14159265358979323846f;
    const float INV_SQRT7 = 0.37796447300922722721f;
    const float SQRT2 = 1.41421356237309504880f;
    for (int idx = t; idx < 32 * 49; idx += 192) {
        int bi = idx / 49, k = idx % 49;
        int tx = k / 7, ty = k % 7;
        float fx = c_lowx[bi], fy = c_lowy[bi];
        float bx = cosf(PI * fx * (tx + 0.5f) / 7.0f) * INV_SQRT7;
        if (fx != 0.0f) bx *= SQRT2;
        float by = cosf(PI * fy * (ty + 0.5f) / 7.0f) * INV_SQRT7;
        if (fy != 0.0f) by *= SQRT2;
        sbasis[idx] = bx * by;
    }
    __syncthreads();

    // yin[c]: last segment i with param[i] <= c < param[i+1] wins
    {
        float cf = (float)t;
        int bid = -1;
        for (int i = 0; i < 32; i++)
            if (cf >= sparam[i] && cf < sparam[i + 1]) bid = i;
        float yv = 0.0f;
        if (bid >= 0) {
            const float* xpp = g_xp + (n * 192 + t) * 49;
            const float* bb = sbasis + bid * 49;
#pragma unroll
            for (int k = 0; k < 49; k++) yv = fmaf(xpp[k], bb[k], yv);
        }
        syin[t] = yv;
    }
    __syncthreads();

    {
        float a = b1d[t];
        for (int c = 0; c < 192; c++) a = fmaf(g_w1dT[c * 192 + t], syin[c], a);
        float sc = bn1g[t] / sqrtf(bn1v[t] + 1e-5f);
        a = (a - bn1m[t]) * sc + bn1b[t];
        g_scale[n * 192 + t] = fmaxf(a, 0.0f);
    }
}

// ---------------------------------------------------------------------------
// Final kernel: out = x * (1 + scale[n,c]).  Reverse address order -> early
// reads hit the x-tail still in L2 after the pool pass; streaming stores keep
// the output from evicting x.
// ---------------------------------------------------------------------------
__global__ __launch_bounds__(256) void final_kernel(
    const float* __restrict__ x, float* __restrict__ out)
{
    const float4* x4 = (const float4*)x;
    float4* o4 = (float4*)out;
    int i = blockIdx.x * blockDim.x + threadIdx.x;
    int r = N4TOT - 1 - i;
    int nc = r / 784;                       // 784 float4 per (n,c) plane
    float s = 1.0f + __ldg(&g_scale[nc]);
    float4 v = __ldg(x4 + r);
    v.x *= s; v.y *= s; v.z *= s; v.w *= s;
    __stcs(o4 + r, v);
}

// ---------------------------------------------------------------------------
// Inputs (metadata order): x, wg1, bn2_g, bn2_b, bn2_m, bn2_v,
//                          wg2, bg2, beta, w1d, b1d, bn1_g, bn1_b, bn1_m, bn1_v
// ---------------------------------------------------------------------------
extern "C" void kernel_launch(void* const* d_in, const int* in_sizes, int n_in,
                              void* d_out, int out_size)
{
    const float* x     = (const float*)d_in[0];
    const float* wg1   = (const float*)d_in[1];
    const float* bn2g  = (const float*)d_in[2];
    const float* bn2b  = (const float*)d_in[3];
    const float* bn2m  = (const float*)d_in[4];
    const float* bn2v  = (const float*)d_in[5];
    const float* wg2   = (const float*)d_in[6];
    const float* bg2   = (const float*)d_in[7];
    const float* beta  = (const float*)d_in[8];
    const float* w1d   = (const float*)d_in[9];
    const float* b1d   = (const float*)d_in[10];
    const float* bn1g  = (const float*)d_in[11];
    const float* bn1b  = (const float*)d_in[12];
    const float* bn1m  = (const float*)d_in[13];
    const float* bn1v  = (const float*)d_in[14];
    float* out = (float*)d_out;

    poolgate_kernel<<<56 + POOLBLK, 448>>>(x, wg1, bn2g, bn2b, bn2m, bn2v, w1d);
    scale_kernel<<<64, 192>>>(wg2, bg2, beta, b1d, bn1g, bn1b, bn1m, bn1v);
    final_kernel<<<N4TOT / 256, 256>>>(x, out);
}